// round 3
// baseline (speedup 1.0000x reference)
#include <cuda_runtime.h>

#define NTOK 4096
#define BATCH 4
#define CIN 256
#define DI 128
#define DV 256
#define OUTC 256

typedef unsigned long long u64;

// ---------------- packed f32x2 helpers (Blackwell FFMA2 path) ----------------
__device__ __forceinline__ void ffma2(u64& d, u64 a, u64 b) {
    asm("fma.rn.f32x2 %0, %1, %2, %0;" : "+l"(d) : "l"(a), "l"(b));
}
__device__ __forceinline__ u64 pack2(float x, float y) {
    u64 r; asm("mov.b64 %0, {%1, %2};" : "=l"(r) : "f"(x), "f"(y)); return r;
}
__device__ __forceinline__ float2 unpack2(u64 a) {
    float2 f; asm("mov.b64 {%0, %1}, %2;" : "=f"(f.x), "=f"(f.y) : "l"(a)); return f;
}
__device__ __forceinline__ u64 mul2(u64 a, u64 b) {
    u64 d; asm("mul.rn.f32x2 %0, %1, %2;" : "=l"(d) : "l"(a), "l"(b)); return d;
}

// ---------------- scratch (no allocations allowed) ----------------
__device__ float g_Q[BATCH * NTOK * DI];     // [b][n][c], pre-scaled by 128^-0.5
__device__ float g_K[BATCH * NTOK * DI];     // [b][m][c]
__device__ float g_V[BATCH * NTOK * DV];     // [b][m][0:128]=v2, [128:256]=v1
__device__ float g_att[BATCH * NTOK * DV];   // [b][n][c]
__device__ float g_csum[BATCH * DV];

__global__ void zero_csum_kernel() {
    g_csum[threadIdx.x] = 0.0f;
}

// colsum[b][vc] = sum_n V[b][n][vc]; grid (64 chunks, B), 256 threads
__global__ void colsum_kernel() {
    const int b = blockIdx.y;
    const int chunk = blockIdx.x;
    const int vc = threadIdx.x;
    const float* base = g_V + ((size_t)b * NTOK + (size_t)chunk * 64) * DV + vc;
    float s = 0.0f;
#pragma unroll 8
    for (int r = 0; r < 64; ++r) s += base[(size_t)r * DV];
    atomicAdd(&g_csum[b * DV + vc], s);
}

// Fused QKV projections. z selects (input, weights, output, stride, prescale).
// out[b][n][o] = relu((sum_c W[o][c]*x[b][c][n] + bias[o])*sc[o] + tr[o]) * prescale
__global__ __launch_bounds__(256)
void qkv_proj_kernel(const float* __restrict__ x1, const float* __restrict__ x2,
                     const float* __restrict__ Wq, const float* __restrict__ bq,
                     const float* __restrict__ sq, const float* __restrict__ tq,
                     const float* __restrict__ Wk, const float* __restrict__ bk,
                     const float* __restrict__ sk, const float* __restrict__ tk,
                     const float* __restrict__ Wv, const float* __restrict__ bv,
                     const float* __restrict__ sv, const float* __restrict__ tv,
                     float* __restrict__ pQ, float* __restrict__ pK, float* __restrict__ pV) {
    __shared__ float Xs[32 * 68];    // [c][n], padded
    __shared__ float Ws[128 * 33];   // [o][c], padded
    const int z = blockIdx.z;
    const float* x; const float* W; const float* bias; const float* sc; const float* tr;
    float* outp; int ostride; float prescale;
    if (z == 0)      { x = x1; W = Wq; bias = bq; sc = sq; tr = tq; outp = pQ;       ostride = DI; prescale = 0.08838834764831845f; }
    else if (z == 1) { x = x2; W = Wk; bias = bk; sc = sk; tr = tk; outp = pK;       ostride = DI; prescale = 1.0f; }
    else if (z == 2) { x = x2; W = Wv; bias = bv; sc = sv; tr = tv; outp = pV;       ostride = DV; prescale = 1.0f; }
    else             { x = x1; W = Wv; bias = bv; sc = sv; tr = tv; outp = pV + DI;  ostride = DV; prescale = 1.0f; }

    const int b = blockIdx.y;
    const int nbase = blockIdx.x * 64;
    const int tid = threadIdx.x;
    const int tx = tid & 15, ty = tid >> 4;
    const float* xg = x + (size_t)b * CIN * NTOK;

    // accp[i2][jj]: row pair (4ty+2*i2, +1) x output col (tx+16*jj)
    u64 accp[2][8];
#pragma unroll
    for (int i = 0; i < 2; ++i)
#pragma unroll
        for (int jj = 0; jj < 8; ++jj) accp[i][jj] = 0ull;

    for (int c0 = 0; c0 < CIN; c0 += 32) {
        __syncthreads();
#pragma unroll
        for (int it = 0; it < 2; ++it) {         // 512 float4 = 32 x 64 floats
            int idx = tid + it * 256;
            int r = idx >> 4, c4 = idx & 15;
            *(float4*)&Xs[r * 68 + c4 * 4] =
                *(const float4*)&xg[(size_t)(c0 + r) * NTOK + nbase + c4 * 4];
        }
#pragma unroll
        for (int it = 0; it < 16; ++it) {        // 4096 floats = 128 x 32
            int idx = tid + it * 256;
            int r = idx >> 5, c = idx & 31;
            Ws[r * 33 + c] = W[(size_t)r * CIN + c0 + c];
        }
        __syncthreads();
#pragma unroll 4
        for (int c = 0; c < 32; ++c) {
            ulonglong2 xp = *(const ulonglong2*)&Xs[c * 68 + 4 * ty];
#pragma unroll
            for (int jj = 0; jj < 8; ++jj) {
                float w = Ws[(tx + 16 * jj) * 33 + c];
                u64 w2 = pack2(w, w);
                ffma2(accp[0][jj], xp.x, w2);
                ffma2(accp[1][jj], xp.y, w2);
            }
        }
    }
#pragma unroll
    for (int jj = 0; jj < 8; ++jj) {
        int o = tx + 16 * jj;
        float bb = bias[o], ss = sc[o], tt = tr[o];
#pragma unroll
        for (int i2 = 0; i2 < 2; ++i2) {
            float2 a = unpack2(accp[i2][jj]);
            float v0 = (a.x + bb) * ss + tt; v0 = v0 > 0.0f ? v0 : 0.0f;
            float v1 = (a.y + bb) * ss + tt; v1 = v1 > 0.0f ? v1 : 0.0f;
            size_t row = (size_t)b * NTOK + nbase + 4 * ty + 2 * i2;
            outp[row * ostride + o] = v0 * prescale;
            outp[(row + 1) * ostride + o] = v1 * prescale;
        }
    }
}

// Flash attention with complement: att[b][n][vc] = csum[b][vc] - softmax(QK^T)·V
// BR=BC=64, D=128, DV=256. 256 threads: tx=tid&15, ty=tid>>4. Packed f32x2 math.
__global__ __launch_bounds__(256, 1)
void attn_kernel(const float* __restrict__ Q, const float* __restrict__ K,
                 const float* __restrict__ V, const float* __restrict__ csum,
                 float* __restrict__ att) {
    extern __shared__ float sm[];
    float* Qs = sm;                       // 64 x 132
    float* Ks = sm + 64 * 132;            // 64 x 132
    float* Vs = sm + 2 * 64 * 132;        // 64 x 260
    float* Ps = Vs + 64 * 260;            // 64 x 68  (P transposed: [m][row])
    const int b = blockIdx.y;
    const int nbase = blockIdx.x * 64;
    const int tid = threadIdx.x;
    const int tx = tid & 15, ty = tid >> 4;

    {
        const float* Qg = Q + ((size_t)b * NTOK + nbase) * DI;
#pragma unroll
        for (int it = 0; it < 8; ++it) {          // 2048 float4
            int idx = tid + it * 256;
            int r = idx >> 5, c4 = idx & 31;
            *(float4*)&Qs[r * 132 + c4 * 4] = *(const float4*)&Qg[(size_t)r * DI + c4 * 4];
        }
    }

    float M[4], L[4];
    // accp[i][2*jj+h]: row 4ty+i, vcols {tx*4+64*jj} packed as 2 f32x2 per float4
    u64 accp[4][8];
#pragma unroll
    for (int i = 0; i < 4; ++i) {
        M[i] = -1e30f; L[i] = 0.0f;
#pragma unroll
        for (int t = 0; t < 8; ++t) accp[i][t] = 0ull;
    }

    for (int mb = 0; mb < NTOK; mb += 64) {
        __syncthreads();  // protects Ks/Vs reuse across iterations & Qs visibility
        {
            const float* Kg = K + ((size_t)b * NTOK + mb) * DI;
#pragma unroll
            for (int it = 0; it < 8; ++it) {
                int idx = tid + it * 256;
                int r = idx >> 5, c4 = idx & 31;
                *(float4*)&Ks[r * 132 + c4 * 4] = *(const float4*)&Kg[(size_t)r * DI + c4 * 4];
            }
            const float* Vg = V + ((size_t)b * NTOK + mb) * DV;
#pragma unroll
            for (int it = 0; it < 16; ++it) {
                int idx = tid + it * 256;
                int r = idx >> 6, c4 = idx & 63;
                *(float4*)&Vs[r * 260 + c4 * 4] = *(const float4*)&Vg[(size_t)r * DV + c4 * 4];
            }
        }
        __syncthreads();

        // ---- S = Q K^T, packed over channel pairs ----
        u64 Sp[4][4];
#pragma unroll
        for (int i = 0; i < 4; ++i)
#pragma unroll
            for (int j = 0; j < 4; ++j) Sp[i][j] = 0ull;

#pragma unroll 2
        for (int c4 = 0; c4 < 32; ++c4) {
            ulonglong2 q[4], k[4];
#pragma unroll
            for (int i = 0; i < 4; ++i)
                q[i] = *(const ulonglong2*)&Qs[(4 * ty + i) * 132 + c4 * 4];
#pragma unroll
            for (int j = 0; j < 4; ++j)
                k[j] = *(const ulonglong2*)&Ks[(tx + 16 * j) * 132 + c4 * 4];
#pragma unroll
            for (int i = 0; i < 4; ++i)
#pragma unroll
                for (int j = 0; j < 4; ++j) {
                    ffma2(Sp[i][j], q[i].x, k[j].x);
                    ffma2(Sp[i][j], q[i].y, k[j].y);
                }
        }
        float S[4][4];
#pragma unroll
        for (int i = 0; i < 4; ++i)
#pragma unroll
            for (int j = 0; j < 4; ++j) {
                float2 f = unpack2(Sp[i][j]);
                S[i][j] = f.x + f.y;
            }

        // ---- online softmax (row groups of 16 lanes share ty) ----
#pragma unroll
        for (int i = 0; i < 4; ++i) {
            float tm = fmaxf(fmaxf(S[i][0], S[i][1]), fmaxf(S[i][2], S[i][3]));
#pragma unroll
            for (int off = 8; off >= 1; off >>= 1)
                tm = fmaxf(tm, __shfl_xor_sync(0xffffffffu, tm, off));
            float newM = fmaxf(M[i], tm);
            float corr = __expf(M[i] - newM);
            float rs = 0.0f;
#pragma unroll
            for (int j = 0; j < 4; ++j) {
                S[i][j] = __expf(S[i][j] - newM);
                rs += S[i][j];
            }
#pragma unroll
            for (int off = 8; off >= 1; off >>= 1)
                rs += __shfl_xor_sync(0xffffffffu, rs, off);
            L[i] = L[i] * corr + rs;
            M[i] = newM;
            u64 c2 = pack2(corr, corr);
#pragma unroll
            for (int t = 0; t < 8; ++t) accp[i][t] = mul2(accp[i][t], c2);
        }
        // store P transposed: Ps[m][row]
#pragma unroll
        for (int j = 0; j < 4; ++j)
            *(float4*)&Ps[(tx + 16 * j) * 68 + 4 * ty] =
                make_float4(S[0][j], S[1][j], S[2][j], S[3][j]);
        __syncthreads();

        // ---- PV (packed): rows 4ty+i, vcols tx*4 + 64*jj ----
#pragma unroll 2
        for (int m = 0; m < 64; ++m) {
            float4 p = *(const float4*)&Ps[m * 68 + 4 * ty];
            u64 pp[4];
            pp[0] = pack2(p.x, p.x); pp[1] = pack2(p.y, p.y);
            pp[2] = pack2(p.z, p.z); pp[3] = pack2(p.w, p.w);
#pragma unroll
            for (int jj = 0; jj < 4; ++jj) {
                ulonglong2 v = *(const ulonglong2*)&Vs[m * 260 + tx * 4 + 64 * jj];
#pragma unroll
                for (int i = 0; i < 4; ++i) {
                    ffma2(accp[i][2 * jj], pp[i], v.x);
                    ffma2(accp[i][2 * jj + 1], pp[i], v.y);
                }
            }
        }
    }

    // ---- epilogue: att = csum - acc / L ----
    const float* cs = csum + b * DV;
    float* og = att + ((size_t)b * NTOK + nbase) * DV;
#pragma unroll
    for (int i = 0; i < 4; ++i) {
        float inv = 1.0f / L[i];
#pragma unroll
        for (int jj = 0; jj < 4; ++jj) {
            int col = tx * 4 + 64 * jj;
            float4 c4 = *(const float4*)&cs[col];
            float2 a0 = unpack2(accp[i][2 * jj]);
            float2 a1 = unpack2(accp[i][2 * jj + 1]);
            float4 r;
            r.x = c4.x - a0.x * inv;
            r.y = c4.y - a0.y * inv;
            r.z = c4.z - a1.x * inv;
            r.w = c4.w - a1.y * inv;
            *(float4*)&og[(size_t)(4 * ty + i) * DV + col] = r;
        }
    }
}

// out[b][o][n] = relu((sum_c Wp[o][c]*att[b][n][c] + bias[o])*sc[o] + tr[o])
// Tile: 64 o x 64 n. grid (NTOK/64, OUTC/64, B). Packed along n.
__global__ __launch_bounds__(256)
void projf_kernel(const float* __restrict__ A, const float* __restrict__ W,
                  const float* __restrict__ bias, const float* __restrict__ sc,
                  const float* __restrict__ tr, float* __restrict__ out) {
    __shared__ float As[32 * 68];   // [c][n]
    __shared__ float Ws[64 * 33];   // [o][c]
    const int b = blockIdx.z;
    const int obase = blockIdx.y * 64;
    const int nbase = blockIdx.x * 64;
    const int tid = threadIdx.x;
    const int tx = tid & 15, ty = tid >> 4;
    const float* Ag = A + (size_t)b * NTOK * DV;

    // accp[i][j2]: o row 4ty+i, n pair (4tx+2*j2, +1)
    u64 accp[4][2];
#pragma unroll
    for (int i = 0; i < 4; ++i) { accp[i][0] = 0ull; accp[i][1] = 0ull; }

    for (int c0 = 0; c0 < DV; c0 += 32) {
        __syncthreads();
#pragma unroll
        for (int it = 0; it < 2; ++it) {     // 512 float4: transpose into As[c][n]
            int idx = tid + it * 256;
            int n = idx >> 3, c4 = idx & 7;
            float4 v = *(const float4*)&Ag[(size_t)(nbase + n) * DV + c0 + c4 * 4];
            As[(c4 * 4 + 0) * 68 + n] = v.x;
            As[(c4 * 4 + 1) * 68 + n] = v.y;
            As[(c4 * 4 + 2) * 68 + n] = v.z;
            As[(c4 * 4 + 3) * 68 + n] = v.w;
        }
#pragma unroll
        for (int it = 0; it < 8; ++it) {     // 2048 floats
            int idx = tid + it * 256;
            int r = idx >> 5, c = idx & 31;
            Ws[r * 33 + c] = W[(size_t)(obase + r) * DV + c0 + c];
        }
        __syncthreads();
#pragma unroll 4
        for (int c = 0; c < 32; ++c) {
            ulonglong2 ap = *(const ulonglong2*)&As[c * 68 + 4 * tx];
#pragma unroll
            for (int i = 0; i < 4; ++i) {
                float w = Ws[(4 * ty + i) * 33 + c];
                u64 w2 = pack2(w, w);
                ffma2(accp[i][0], w2, ap.x);
                ffma2(accp[i][1], w2, ap.y);
            }
        }
    }
#pragma unroll
    for (int i = 0; i < 4; ++i) {
        int o = obase + 4 * ty + i;
        float bb = bias[o], ss = sc[o], tt = tr[o];
        float2 a0 = unpack2(accp[i][0]);
        float2 a1 = unpack2(accp[i][1]);
        float4 r;
        r.x = (a0.x + bb) * ss + tt; r.x = r.x > 0.f ? r.x : 0.f;
        r.y = (a0.y + bb) * ss + tt; r.y = r.y > 0.f ? r.y : 0.f;
        r.z = (a1.x + bb) * ss + tt; r.z = r.z > 0.f ? r.z : 0.f;
        r.w = (a1.y + bb) * ss + tt; r.w = r.w > 0.f ? r.w : 0.f;
        *(float4*)&out[((size_t)b * OUTC + o) * NTOK + nbase + 4 * tx] = r;
    }
}

extern "C" void kernel_launch(void* const* d_in, const int* in_sizes, int n_in,
                              void* d_out, int out_size) {
    const float* x1 = (const float*)d_in[0];
    const float* x2 = (const float*)d_in[1];
    const float* Wq = (const float*)d_in[2];
    const float* bq = (const float*)d_in[3];
    const float* sq = (const float*)d_in[4];
    const float* tq = (const float*)d_in[5];
    const float* Wk = (const float*)d_in[6];
    const float* bk = (const float*)d_in[7];
    const float* sk = (const float*)d_in[8];
    const float* tk = (const float*)d_in[9];
    const float* Wv = (const float*)d_in[10];
    const float* bv = (const float*)d_in[11];
    const float* sv = (const float*)d_in[12];
    const float* tv = (const float*)d_in[13];
    const float* Wp = (const float*)d_in[14];
    const float* bp = (const float*)d_in[15];
    const float* sp = (const float*)d_in[16];
    const float* tp = (const float*)d_in[17];
    float* out = (float*)d_out;

    float *pQ, *pK, *pV, *pAtt, *pCs;
    cudaGetSymbolAddress((void**)&pQ, g_Q);
    cudaGetSymbolAddress((void**)&pK, g_K);
    cudaGetSymbolAddress((void**)&pV, g_V);
    cudaGetSymbolAddress((void**)&pAtt, g_att);
    cudaGetSymbolAddress((void**)&pCs, g_csum);

    const int SMEM_ATTN = (64 * 132 * 2 + 64 * 260 + 64 * 68) * 4;  // 151552 B
    cudaFuncSetAttribute(attn_kernel, cudaFuncAttributeMaxDynamicSharedMemorySize, SMEM_ATTN);

    // Fused QKV projections: z=0 Q(x1), z=1 K(x2), z=2 V(x2)->cols[0,128), z=3 V(x1)->cols[128,256)
    qkv_proj_kernel<<<dim3(NTOK / 64, BATCH, 4), 256>>>(
        x1, x2, Wq, bq, sq, tq, Wk, bk, sk, tk, Wv, bv, sv, tv, pQ, pK, pV);
    zero_csum_kernel<<<1, BATCH * DV>>>();
    colsum_kernel<<<dim3(NTOK / 64, BATCH), 256>>>();
    attn_kernel<<<dim3(NTOK / 64, BATCH), 256, SMEM_ATTN>>>(pQ, pK, pV, pCs, pAtt);
    projf_kernel<<<dim3(NTOK / 64, OUTC / 64, BATCH), 256>>>(pAtt, Wp, bp, sp, tp, out);
}

// round 4
// speedup vs baseline: 3.0128x; 3.0128x over previous
#include <cuda_runtime.h>
#include <cstdint>

#define NTOK 4096
#define BATCH 4
#define CIN 256
#define DI 128
#define DV 256
#define OUTC 256

typedef unsigned long long u64;
typedef uint32_t u32;

// ---------------- packed f32x2 helpers ----------------
__device__ __forceinline__ void ffma2(u64& d, u64 a, u64 b) {
    asm("fma.rn.f32x2 %0, %1, %2, %0;" : "+l"(d) : "l"(a), "l"(b));
}
__device__ __forceinline__ u64 pack2(float x, float y) {
    u64 r; asm("mov.b64 %0, {%1, %2};" : "=l"(r) : "f"(x), "f"(y)); return r;
}
__device__ __forceinline__ float2 unpack2(u64 a) {
    float2 f; asm("mov.b64 {%0, %1}, %2;" : "=f"(f.x), "=f"(f.y) : "l"(a)); return f;
}

// ---------------- tf32 mma helpers ----------------
__device__ __forceinline__ u32 f2tf(float f) {
    u32 u; asm("cvt.rna.tf32.f32 %0, %1;" : "=r"(u) : "f"(f)); return u;
}
__device__ __forceinline__ void mma8(float4& d, u32 a0, u32 a1, u32 a2, u32 a3,
                                     u32 b0, u32 b1) {
    asm volatile(
        "mma.sync.aligned.m16n8k8.row.col.f32.tf32.tf32.f32 "
        "{%0,%1,%2,%3}, {%4,%5,%6,%7}, {%8,%9}, {%0,%1,%2,%3};"
        : "+f"(d.x), "+f"(d.y), "+f"(d.z), "+f"(d.w)
        : "r"(a0), "r"(a1), "r"(a2), "r"(a3), "r"(b0), "r"(b1));
}

// ---------------- scratch ----------------
__device__ float g_Q[BATCH * NTOK * DI];     // [b][n][c], pre-scaled by 128^-0.5
__device__ float g_K[BATCH * NTOK * DI];     // [b][m][c]
__device__ float g_V[BATCH * NTOK * DV];     // [b][m][0:128]=v2, [128:256]=v1
__device__ float g_att[BATCH * NTOK * DV];   // [b][n][c]
__device__ float g_csum[BATCH * DV];

__global__ void zero_csum_kernel() { g_csum[threadIdx.x] = 0.0f; }

__global__ void colsum_kernel() {
    const int b = blockIdx.y;
    const int chunk = blockIdx.x;
    const int vc = threadIdx.x;
    const float* base = g_V + ((size_t)b * NTOK + (size_t)chunk * 64) * DV + vc;
    float s = 0.0f;
#pragma unroll 8
    for (int r = 0; r < 64; ++r) s += base[(size_t)r * DV];
    atomicAdd(&g_csum[b * DV + vc], s);
}

// Fused QKV projections (fp32, f32x2 inner loop). z selects variant.
__global__ __launch_bounds__(256)
void qkv_proj_kernel(const float* __restrict__ x1, const float* __restrict__ x2,
                     const float* __restrict__ Wq, const float* __restrict__ bq,
                     const float* __restrict__ sq, const float* __restrict__ tq,
                     const float* __restrict__ Wk, const float* __restrict__ bk,
                     const float* __restrict__ sk, const float* __restrict__ tk,
                     const float* __restrict__ Wv, const float* __restrict__ bv,
                     const float* __restrict__ sv, const float* __restrict__ tv,
                     float* __restrict__ pQ, float* __restrict__ pK, float* __restrict__ pV) {
    __shared__ float Xs[32 * 68];
    __shared__ float Ws[128 * 33];
    const int z = blockIdx.z;
    const float* x; const float* W; const float* bias; const float* sc; const float* tr;
    float* outp; int ostride; float prescale;
    if (z == 0)      { x = x1; W = Wq; bias = bq; sc = sq; tr = tq; outp = pQ;      ostride = DI; prescale = 0.08838834764831845f; }
    else if (z == 1) { x = x2; W = Wk; bias = bk; sc = sk; tr = tk; outp = pK;      ostride = DI; prescale = 1.0f; }
    else if (z == 2) { x = x2; W = Wv; bias = bv; sc = sv; tr = tv; outp = pV;      ostride = DV; prescale = 1.0f; }
    else             { x = x1; W = Wv; bias = bv; sc = sv; tr = tv; outp = pV + DI; ostride = DV; prescale = 1.0f; }

    const int b = blockIdx.y;
    const int nbase = blockIdx.x * 64;
    const int tid = threadIdx.x;
    const int tx = tid & 15, ty = tid >> 4;
    const float* xg = x + (size_t)b * CIN * NTOK;

    u64 accp[2][8];
#pragma unroll
    for (int i = 0; i < 2; ++i)
#pragma unroll
        for (int jj = 0; jj < 8; ++jj) accp[i][jj] = 0ull;

    for (int c0 = 0; c0 < CIN; c0 += 32) {
        __syncthreads();
#pragma unroll
        for (int it = 0; it < 2; ++it) {
            int idx = tid + it * 256;
            int r = idx >> 4, c4 = idx & 15;
            *(float4*)&Xs[r * 68 + c4 * 4] =
                *(const float4*)&xg[(size_t)(c0 + r) * NTOK + nbase + c4 * 4];
        }
#pragma unroll
        for (int it = 0; it < 16; ++it) {
            int idx = tid + it * 256;
            int r = idx >> 5, c = idx & 31;
            Ws[r * 33 + c] = W[(size_t)r * CIN + c0 + c];
        }
        __syncthreads();
#pragma unroll 4
        for (int c = 0; c < 32; ++c) {
            ulonglong2 xp = *(const ulonglong2*)&Xs[c * 68 + 4 * ty];
#pragma unroll
            for (int jj = 0; jj < 8; ++jj) {
                float w = Ws[(tx + 16 * jj) * 33 + c];
                u64 w2 = pack2(w, w);
                ffma2(accp[0][jj], xp.x, w2);
                ffma2(accp[1][jj], xp.y, w2);
            }
        }
    }
#pragma unroll
    for (int jj = 0; jj < 8; ++jj) {
        int o = tx + 16 * jj;
        float bb = bias[o], ss = sc[o], tt = tr[o];
#pragma unroll
        for (int i2 = 0; i2 < 2; ++i2) {
            float2 a = unpack2(accp[i2][jj]);
            float v0 = (a.x + bb) * ss + tt; v0 = v0 > 0.0f ? v0 : 0.0f;
            float v1 = (a.y + bb) * ss + tt; v1 = v1 > 0.0f ? v1 : 0.0f;
            size_t row = (size_t)b * NTOK + nbase + 4 * ty + 2 * i2;
            outp[row * ostride + o] = v0 * prescale;
            outp[(row + 1) * ostride + o] = v1 * prescale;
        }
    }
}

// ============================================================================
// Flash attention w/ complement, tf32 tensor cores (mma.sync m16n8k8).
// att[b][n][vc] = csum[b][vc] - softmax(QK^T)[n][m] · V[m][vc]
// BR=BC=64, D=128, DV=256. 256 threads = 8 warps in a 4(row) x 2(col) grid.
//   warp r = wid>>1 owns S-rows [16r,16r+16); warp c = wid&1 owns
//   S-cols [32c,32c+32) in QK phase and V-cols [128c,128c+128) in PV phase.
// ============================================================================
__global__ __launch_bounds__(256, 1)
void attn_kernel(const float* __restrict__ Q, const float* __restrict__ K,
                 const float* __restrict__ V, const float* __restrict__ csum,
                 float* __restrict__ att) {
    extern __shared__ u32 sm[];
    u32* Qs = sm;                       // 64 x 132 (tf32)
    u32* Ks = Qs + 64 * 132;            // 64 x 132 (tf32)
    u32* Vs = Ks + 64 * 132;            // 64 x 260 (tf32)
    u32* Ps = Vs + 64 * 260;            // 64 x 68  (tf32 probs, [row][m])
    float* red = (float*)(Ps + 64 * 68);  // [0:128) max partials, [128:256) sum partials

    const int b = blockIdx.y;
    const int nbase = blockIdx.x * 64;
    const int tid = threadIdx.x;
    const int wid = tid >> 5, lane = tid & 31;
    const int wr = wid >> 1, wc = wid & 1;
    const int gq = lane >> 2, qd = lane & 3;   // group (0..7), quad lane (0..3)
    const int row0 = 16 * wr + gq;             // thread's S/O row (and row0+8)

    // ---- load Q tile (convert to tf32) ----
    {
        const float* Qg = Q + ((size_t)b * NTOK + nbase) * DI;
#pragma unroll
        for (int it = 0; it < 8; ++it) {
            int idx = tid + it * 256;
            int r = idx >> 5, c4 = idx & 31;
            float4 v = *(const float4*)&Qg[(size_t)r * DI + c4 * 4];
            uint4 u = make_uint4(f2tf(v.x), f2tf(v.y), f2tf(v.z), f2tf(v.w));
            *(uint4*)&Qs[r * 132 + c4 * 4] = u;
        }
    }

    float M0 = -1e30f, M1 = -1e30f, L0 = 0.0f, L1 = 0.0f;
    float4 acc[16];                      // O accum: tile t -> cols 128*wc+8t+2qd(+1)
#pragma unroll
    for (int t = 0; t < 16; ++t) acc[t] = make_float4(0.f, 0.f, 0.f, 0.f);

    for (int mb = 0; mb < NTOK; mb += 64) {
        __syncthreads();  // prev iter's PV reads of Ks/Vs/Ps complete
        {
            const float* Kg = K + ((size_t)b * NTOK + mb) * DI;
#pragma unroll
            for (int it = 0; it < 8; ++it) {
                int idx = tid + it * 256;
                int r = idx >> 5, c4 = idx & 31;
                float4 v = *(const float4*)&Kg[(size_t)r * DI + c4 * 4];
                uint4 u = make_uint4(f2tf(v.x), f2tf(v.y), f2tf(v.z), f2tf(v.w));
                *(uint4*)&Ks[r * 132 + c4 * 4] = u;
            }
            const float* Vg = V + ((size_t)b * NTOK + mb) * DV;
#pragma unroll
            for (int it = 0; it < 16; ++it) {
                int idx = tid + it * 256;
                int r = idx >> 6, c4 = idx & 63;
                float4 v = *(const float4*)&Vg[(size_t)r * DV + c4 * 4];
                uint4 u = make_uint4(f2tf(v.x), f2tf(v.y), f2tf(v.z), f2tf(v.w));
                *(uint4*)&Vs[r * 260 + c4 * 4] = u;
            }
        }
        __syncthreads();

        // ---- S = Q K^T (warp computes 16x32) ----
        float4 S[4];
#pragma unroll
        for (int t = 0; t < 4; ++t) S[t] = make_float4(0.f, 0.f, 0.f, 0.f);
#pragma unroll
        for (int kk = 0; kk < 16; ++kk) {
            int k = kk * 8 + qd;
            u32 a0 = Qs[row0 * 132 + k];
            u32 a1 = Qs[(row0 + 8) * 132 + k];
            u32 a2 = Qs[row0 * 132 + k + 4];
            u32 a3 = Qs[(row0 + 8) * 132 + k + 4];
#pragma unroll
            for (int t = 0; t < 4; ++t) {
                int n = 32 * wc + 8 * t + gq;
                u32 b0 = Ks[n * 132 + k];
                u32 b1 = Ks[n * 132 + k + 4];
                mma8(S[t], a0, a1, a2, a3, b0, b1);
            }
        }

        // ---- row max (thread-local -> quad shuffle -> cross-warp via smem) ----
        float mx0 = fmaxf(fmaxf(S[0].x, S[0].y), fmaxf(S[1].x, S[1].y));
        mx0 = fmaxf(mx0, fmaxf(fmaxf(S[2].x, S[2].y), fmaxf(S[3].x, S[3].y)));
        float mx1 = fmaxf(fmaxf(S[0].z, S[0].w), fmaxf(S[1].z, S[1].w));
        mx1 = fmaxf(mx1, fmaxf(fmaxf(S[2].z, S[2].w), fmaxf(S[3].z, S[3].w)));
        mx0 = fmaxf(mx0, __shfl_xor_sync(0xffffffffu, mx0, 1));
        mx0 = fmaxf(mx0, __shfl_xor_sync(0xffffffffu, mx0, 2));
        mx1 = fmaxf(mx1, __shfl_xor_sync(0xffffffffu, mx1, 1));
        mx1 = fmaxf(mx1, __shfl_xor_sync(0xffffffffu, mx1, 2));
        if (qd == 0) {
            red[wc * 64 + row0] = mx0;
            red[wc * 64 + row0 + 8] = mx1;
        }
        __syncthreads();
        float newM0 = fmaxf(M0, fmaxf(red[row0], red[64 + row0]));
        float newM1 = fmaxf(M1, fmaxf(red[row0 + 8], red[64 + row0 + 8]));

        // ---- exp + partial sums + store P (tf32) ----
        float s0 = 0.0f, s1 = 0.0f;
#pragma unroll
        for (int t = 0; t < 4; ++t) {
            S[t].x = __expf(S[t].x - newM0);
            S[t].y = __expf(S[t].y - newM0);
            S[t].z = __expf(S[t].z - newM1);
            S[t].w = __expf(S[t].w - newM1);
            s0 += S[t].x + S[t].y;
            s1 += S[t].z + S[t].w;
            int col = 32 * wc + 8 * t + 2 * qd;
            *(uint2*)&Ps[row0 * 68 + col] = make_uint2(f2tf(S[t].x), f2tf(S[t].y));
            *(uint2*)&Ps[(row0 + 8) * 68 + col] = make_uint2(f2tf(S[t].z), f2tf(S[t].w));
        }
        s0 += __shfl_xor_sync(0xffffffffu, s0, 1);
        s0 += __shfl_xor_sync(0xffffffffu, s0, 2);
        s1 += __shfl_xor_sync(0xffffffffu, s1, 1);
        s1 += __shfl_xor_sync(0xffffffffu, s1, 2);
        if (qd == 0) {
            red[128 + wc * 64 + row0] = s0;
            red[128 + wc * 64 + row0 + 8] = s1;
        }
        __syncthreads();
        float corr0 = __expf(M0 - newM0);
        float corr1 = __expf(M1 - newM1);
        L0 = L0 * corr0 + red[128 + row0] + red[192 + row0];
        L1 = L1 * corr1 + red[128 + row0 + 8] + red[192 + row0 + 8];
        M0 = newM0; M1 = newM1;
#pragma unroll
        for (int t = 0; t < 16; ++t) {
            acc[t].x *= corr0; acc[t].y *= corr0;
            acc[t].z *= corr1; acc[t].w *= corr1;
        }

        // ---- O += P V (warp computes 16x128 at vc base 128*wc) ----
#pragma unroll
        for (int kk = 0; kk < 8; ++kk) {
            int k = kk * 8 + qd;
            u32 a0 = Ps[row0 * 68 + k];
            u32 a1 = Ps[(row0 + 8) * 68 + k];
            u32 a2 = Ps[row0 * 68 + k + 4];
            u32 a3 = Ps[(row0 + 8) * 68 + k + 4];
            int m0 = kk * 8 + qd;
#pragma unroll
            for (int t = 0; t < 16; ++t) {
                int vc = 128 * wc + 8 * t + gq;
                u32 b0 = Vs[m0 * 260 + vc];
                u32 b1 = Vs[(m0 + 4) * 260 + vc];
                mma8(acc[t], a0, a1, a2, a3, b0, b1);
            }
        }
    }

    // ---- epilogue: att = csum - acc / L ----
    const float* cs = csum + b * DV;
    float* og = att + ((size_t)b * NTOK + nbase) * DV;
    float inv0 = 1.0f / L0, inv1 = 1.0f / L1;
#pragma unroll
    for (int t = 0; t < 16; ++t) {
        int col = 128 * wc + 8 * t + 2 * qd;
        float2 c0 = *(const float2*)&cs[col];
        float2 r0, r1;
        r0.x = c0.x - acc[t].x * inv0;
        r0.y = c0.y - acc[t].y * inv0;
        r1.x = c0.x - acc[t].z * inv1;
        r1.y = c0.y - acc[t].w * inv1;
        *(float2*)&og[(size_t)row0 * DV + col] = r0;
        *(float2*)&og[(size_t)(row0 + 8) * DV + col] = r1;
    }
}

// out[b][o][n] = relu((sum_c Wp[o][c]*att[b][n][c] + bias[o])*sc[o] + tr[o])
__global__ __launch_bounds__(256)
void projf_kernel(const float* __restrict__ A, const float* __restrict__ W,
                  const float* __restrict__ bias, const float* __restrict__ sc,
                  const float* __restrict__ tr, float* __restrict__ out) {
    __shared__ float As[32 * 68];
    __shared__ float Ws[64 * 33];
    const int b = blockIdx.z;
    const int obase = blockIdx.y * 64;
    const int nbase = blockIdx.x * 64;
    const int tid = threadIdx.x;
    const int tx = tid & 15, ty = tid >> 4;
    const float* Ag = A + (size_t)b * NTOK * DV;

    u64 accp[4][2];
#pragma unroll
    for (int i = 0; i < 4; ++i) { accp[i][0] = 0ull; accp[i][1] = 0ull; }

    for (int c0 = 0; c0 < DV; c0 += 32) {
        __syncthreads();
#pragma unroll
        for (int it = 0; it < 2; ++it) {
            int idx = tid + it * 256;
            int n = idx >> 3, c4 = idx & 7;
            float4 v = *(const float4*)&Ag[(size_t)(nbase + n) * DV + c0 + c4 * 4];
            As[(c4 * 4 + 0) * 68 + n] = v.x;
            As[(c4 * 4 + 1) * 68 + n] = v.y;
            As[(c4 * 4 + 2) * 68 + n] = v.z;
            As[(c4 * 4 + 3) * 68 + n] = v.w;
        }
#pragma unroll
        for (int it = 0; it < 8; ++it) {
            int idx = tid + it * 256;
            int r = idx >> 5, c = idx & 31;
            Ws[r * 33 + c] = W[(size_t)(obase + r) * DV + c0 + c];
        }
        __syncthreads();
#pragma unroll 4
        for (int c = 0; c < 32; ++c) {
            ulonglong2 ap = *(const ulonglong2*)&As[c * 68 + 4 * tx];
#pragma unroll
            for (int i = 0; i < 4; ++i) {
                float w = Ws[(4 * ty + i) * 33 + c];
                u64 w2 = pack2(w, w);
                ffma2(accp[i][0], w2, ap.x);
                ffma2(accp[i][1], w2, ap.y);
            }
        }
    }
#pragma unroll
    for (int i = 0; i < 4; ++i) {
        int o = obase + 4 * ty + i;
        float bb = bias[o], ss = sc[o], tt = tr[o];
        float2 a0 = unpack2(accp[i][0]);
        float2 a1 = unpack2(accp[i][1]);
        float4 r;
        r.x = (a0.x + bb) * ss + tt; r.x = r.x > 0.f ? r.x : 0.f;
        r.y = (a0.y + bb) * ss + tt; r.y = r.y > 0.f ? r.y : 0.f;
        r.z = (a1.x + bb) * ss + tt; r.z = r.z > 0.f ? r.z : 0.f;
        r.w = (a1.y + bb) * ss + tt; r.w = r.w > 0.f ? r.w : 0.f;
        *(float4*)&out[((size_t)b * OUTC + o) * NTOK + nbase + 4 * tx] = r;
    }
}

extern "C" void kernel_launch(void* const* d_in, const int* in_sizes, int n_in,
                              void* d_out, int out_size) {
    const float* x1 = (const float*)d_in[0];
    const float* x2 = (const float*)d_in[1];
    const float* Wq = (const float*)d_in[2];
    const float* bq = (const float*)d_in[3];
    const float* sq = (const float*)d_in[4];
    const float* tq = (const float*)d_in[5];
    const float* Wk = (const float*)d_in[6];
    const float* bk = (const float*)d_in[7];
    const float* sk = (const float*)d_in[8];
    const float* tk = (const float*)d_in[9];
    const float* Wv = (const float*)d_in[10];
    const float* bv = (const float*)d_in[11];
    const float* sv = (const float*)d_in[12];
    const float* tv = (const float*)d_in[13];
    const float* Wp = (const float*)d_in[14];
    const float* bp = (const float*)d_in[15];
    const float* sp = (const float*)d_in[16];
    const float* tp = (const float*)d_in[17];
    float* out = (float*)d_out;

    float *pQ, *pK, *pV, *pAtt, *pCs;
    cudaGetSymbolAddress((void**)&pQ, g_Q);
    cudaGetSymbolAddress((void**)&pK, g_K);
    cudaGetSymbolAddress((void**)&pV, g_V);
    cudaGetSymbolAddress((void**)&pAtt, g_att);
    cudaGetSymbolAddress((void**)&pCs, g_csum);

    // Qs+Ks (64x132 each) + Vs (64x260) + Ps (64x68) + red (256 floats)
    const int SMEM_ATTN = (64 * 132 * 2 + 64 * 260 + 64 * 68 + 256) * 4;  // 152576 B
    cudaFuncSetAttribute(attn_kernel, cudaFuncAttributeMaxDynamicSharedMemorySize, SMEM_ATTN);

    qkv_proj_kernel<<<dim3(NTOK / 64, BATCH, 4), 256>>>(
        x1, x2, Wq, bq, sq, tq, Wk, bk, sk, tk, Wv, bv, sv, tv, pQ, pK, pV);
    zero_csum_kernel<<<1, BATCH * DV>>>();
    colsum_kernel<<<dim3(NTOK / 64, BATCH), 256>>>();
    attn_kernel<<<dim3(NTOK / 64, BATCH), 256, SMEM_ATTN>>>(pQ, pK, pV, pCs, pAtt);
    projf_kernel<<<dim3(NTOK / 64, OUTC / 64, BATCH), 256>>>(pAtt, Wp, bp, sp, tp, out);
}

// round 5
// speedup vs baseline: 3.2028x; 1.0631x over previous
#include <cuda_runtime.h>
#include <cstdint>

#define NTOK 4096
#define BATCH 4
#define CIN 256
#define DI 128
#define DV 256
#define OUTC 256

typedef unsigned long long u64;
typedef uint32_t u32;

// ---------------- packed f32x2 helpers ----------------
__device__ __forceinline__ void ffma2(u64& d, u64 a, u64 b) {
    asm("fma.rn.f32x2 %0, %1, %2, %0;" : "+l"(d) : "l"(a), "l"(b));
}
__device__ __forceinline__ u64 pack2(float x, float y) {
    u64 r; asm("mov.b64 %0, {%1, %2};" : "=l"(r) : "f"(x), "f"(y)); return r;
}
__device__ __forceinline__ float2 unpack2(u64 a) {
    float2 f; asm("mov.b64 {%0, %1}, %2;" : "=f"(f.x), "=f"(f.y) : "l"(a)); return f;
}

// ---------------- tf32 mma (raw fp32 bits: HW reads bits[31:13]) ----------------
__device__ __forceinline__ void mma8(float4& d, u32 a0, u32 a1, u32 a2, u32 a3,
                                     u32 b0, u32 b1) {
    asm volatile(
        "mma.sync.aligned.m16n8k8.row.col.f32.tf32.tf32.f32 "
        "{%0,%1,%2,%3}, {%4,%5,%6,%7}, {%8,%9}, {%0,%1,%2,%3};"
        : "+f"(d.x), "+f"(d.y), "+f"(d.z), "+f"(d.w)
        : "r"(a0), "r"(a1), "r"(a2), "r"(a3), "r"(b0), "r"(b1));
}

// ---------------- cp.async helpers ----------------
__device__ __forceinline__ u32 smaddr(const void* p) {
    return (u32)__cvta_generic_to_shared(p);
}
__device__ __forceinline__ void cp16(u32 dst, const void* src) {
    asm volatile("cp.async.cg.shared.global [%0], [%1], 16;" :: "r"(dst), "l"(src));
}
#define CP_COMMIT() asm volatile("cp.async.commit_group;")
#define CP_WAIT1()  asm volatile("cp.async.wait_group 1;")
#define CP_WAIT0()  asm volatile("cp.async.wait_group 0;")

// ---------------- scratch ----------------
__device__ float g_Q[BATCH * NTOK * DI];     // [b][n][c], pre-scaled by 128^-0.5
__device__ float g_K[BATCH * NTOK * DI];     // [b][m][c]
__device__ float g_V[BATCH * NTOK * DV];     // [b][m][0:128]=v2, [128:256]=v1
__device__ float g_att[BATCH * NTOK * DV];   // [b][n][c]
__device__ float g_csum[BATCH * DV];

__global__ void zero_csum_kernel() { g_csum[threadIdx.x] = 0.0f; }

__global__ void colsum_kernel() {
    const int b = blockIdx.y;
    const int chunk = blockIdx.x;
    const int vc = threadIdx.x;
    const float* base = g_V + ((size_t)b * NTOK + (size_t)chunk * 64) * DV + vc;
    float s = 0.0f;
#pragma unroll 8
    for (int r = 0; r < 64; ++r) s += base[(size_t)r * DV];
    atomicAdd(&g_csum[b * DV + vc], s);
}

// Fused QKV projections (fp32, f32x2 inner loop). z selects variant.
__global__ __launch_bounds__(256)
void qkv_proj_kernel(const float* __restrict__ x1, const float* __restrict__ x2,
                     const float* __restrict__ Wq, const float* __restrict__ bq,
                     const float* __restrict__ sq, const float* __restrict__ tq,
                     const float* __restrict__ Wk, const float* __restrict__ bk,
                     const float* __restrict__ sk, const float* __restrict__ tk,
                     const float* __restrict__ Wv, const float* __restrict__ bv,
                     const float* __restrict__ sv, const float* __restrict__ tv,
                     float* __restrict__ pQ, float* __restrict__ pK, float* __restrict__ pV) {
    __shared__ float Xs[32 * 68];
    __shared__ float Ws[128 * 33];
    const int z = blockIdx.z;
    const float* x; const float* W; const float* bias; const float* sc; const float* tr;
    float* outp; int ostride; float prescale;
    if (z == 0)      { x = x1; W = Wq; bias = bq; sc = sq; tr = tq; outp = pQ;      ostride = DI; prescale = 0.08838834764831845f; }
    else if (z == 1) { x = x2; W = Wk; bias = bk; sc = sk; tr = tk; outp = pK;      ostride = DI; prescale = 1.0f; }
    else if (z == 2) { x = x2; W = Wv; bias = bv; sc = sv; tr = tv; outp = pV;      ostride = DV; prescale = 1.0f; }
    else             { x = x1; W = Wv; bias = bv; sc = sv; tr = tv; outp = pV + DI; ostride = DV; prescale = 1.0f; }

    const int b = blockIdx.y;
    const int nbase = blockIdx.x * 64;
    const int tid = threadIdx.x;
    const int tx = tid & 15, ty = tid >> 4;
    const float* xg = x + (size_t)b * CIN * NTOK;

    u64 accp[2][8];
#pragma unroll
    for (int i = 0; i < 2; ++i)
#pragma unroll
        for (int jj = 0; jj < 8; ++jj) accp[i][jj] = 0ull;

    for (int c0 = 0; c0 < CIN; c0 += 32) {
        __syncthreads();
#pragma unroll
        for (int it = 0; it < 2; ++it) {
            int idx = tid + it * 256;
            int r = idx >> 4, c4 = idx & 15;
            *(float4*)&Xs[r * 68 + c4 * 4] =
                *(const float4*)&xg[(size_t)(c0 + r) * NTOK + nbase + c4 * 4];
        }
#pragma unroll
        for (int it = 0; it < 16; ++it) {
            int idx = tid + it * 256;
            int r = idx >> 5, c = idx & 31;
            Ws[r * 33 + c] = W[(size_t)r * CIN + c0 + c];
        }
        __syncthreads();
#pragma unroll 4
        for (int c = 0; c < 32; ++c) {
            ulonglong2 xp = *(const ulonglong2*)&Xs[c * 68 + 4 * ty];
#pragma unroll
            for (int jj = 0; jj < 8; ++jj) {
                float w = Ws[(tx + 16 * jj) * 33 + c];
                u64 w2 = pack2(w, w);
                ffma2(accp[0][jj], xp.x, w2);
                ffma2(accp[1][jj], xp.y, w2);
            }
        }
    }
#pragma unroll
    for (int jj = 0; jj < 8; ++jj) {
        int o = tx + 16 * jj;
        float bb = bias[o], ss = sc[o], tt = tr[o];
#pragma unroll
        for (int i2 = 0; i2 < 2; ++i2) {
            float2 a = unpack2(accp[i2][jj]);
            float v0 = (a.x + bb) * ss + tt; v0 = v0 > 0.0f ? v0 : 0.0f;
            float v1 = (a.y + bb) * ss + tt; v1 = v1 > 0.0f ? v1 : 0.0f;
            size_t row = (size_t)b * NTOK + nbase + 4 * ty + 2 * i2;
            outp[row * ostride + o] = v0 * prescale;
            outp[(row + 1) * ostride + o] = v1 * prescale;
        }
    }
}

// ============================================================================
// Flash attention w/ complement, tf32 mma on RAW fp32 bits, cp.async pipelined.
// att[b][n][vc] = csum[b][vc] - softmax(QK^T)[n][m] · V[m][vc]
// BR=BC=64, D=128, DV=256. 8 warps: 4(row) x 2(col).
// Single-buffer pipeline: K(mb+1) loads during softmax+PV(mb);
// V(mb) loads during S(mb).
// ============================================================================
__global__ __launch_bounds__(256, 1)
void attn_kernel(const float* __restrict__ Q, const float* __restrict__ K,
                 const float* __restrict__ V, const float* __restrict__ csum,
                 float* __restrict__ att) {
    extern __shared__ u32 sm[];
    u32* Qs = sm;                       // 64 x 132
    u32* Ks = Qs + 64 * 132;            // 64 x 132
    u32* Vs = Ks + 64 * 132;            // 64 x 260
    u32* Ps = Vs + 64 * 260;            // 64 x 68  (probs, raw fp32 bits, [row][m])
    float* red = (float*)(Ps + 64 * 68);  // [0:128) max partials, [128:256) sums

    const int b = blockIdx.y;
    const int nbase = blockIdx.x * 64;
    const int tid = threadIdx.x;
    const int wid = tid >> 5, lane = tid & 31;
    const int wr = wid >> 1, wc = wid & 1;
    const int gq = lane >> 2, qd = lane & 3;
    const int row0 = 16 * wr + gq;

    // per-thread cp.async slots (raw bytes, no conversion)
    const int rK = tid >> 5, cK = (tid & 31) * 4;        // K/Q: 8 iters of (r+8it)
    const int rV = tid >> 6, cV = (tid & 63) * 4;        // V: 16 iters of (r+4it)
    const float* Qg = Q + ((size_t)b * NTOK + nbase) * DI;
    const float* Kg0 = K + (size_t)b * NTOK * DI;
    const float* Vg0 = V + (size_t)b * NTOK * DV;

    // ---- prologue: group A = Q + K(0); group B = V(0) ----
#pragma unroll
    for (int it = 0; it < 8; ++it) {
        int r = rK + 8 * it;
        cp16(smaddr(&Qs[r * 132 + cK]), Qg + (size_t)r * DI + cK);
        cp16(smaddr(&Ks[r * 132 + cK]), Kg0 + (size_t)r * DI + cK);
    }
    CP_COMMIT();
#pragma unroll
    for (int it = 0; it < 16; ++it) {
        int r = rV + 4 * it;
        cp16(smaddr(&Vs[r * 260 + cV]), Vg0 + (size_t)r * DV + cV);
    }
    CP_COMMIT();

    float M0 = -1e30f, M1 = -1e30f, L0 = 0.0f, L1 = 0.0f;
    float4 acc[16];
#pragma unroll
    for (int t = 0; t < 16; ++t) acc[t] = make_float4(0.f, 0.f, 0.f, 0.f);

    for (int mb = 0; mb < NTOK; mb += 64) {
        const bool more = (mb + 64) < NTOK;
        // K(mb) (and Q on first iter) ready; V(mb) may still be in flight
        CP_WAIT1();
        __syncthreads();

        // ---- S = Q K^T (warp computes 16x32) ----
        float4 S[4];
#pragma unroll
        for (int t = 0; t < 4; ++t) S[t] = make_float4(0.f, 0.f, 0.f, 0.f);
#pragma unroll
        for (int kk = 0; kk < 16; ++kk) {
            int k = kk * 8 + qd;
            u32 a0 = Qs[row0 * 132 + k];
            u32 a1 = Qs[(row0 + 8) * 132 + k];
            u32 a2 = Qs[row0 * 132 + k + 4];
            u32 a3 = Qs[(row0 + 8) * 132 + k + 4];
#pragma unroll
            for (int t = 0; t < 4; ++t) {
                int n = 32 * wc + 8 * t + gq;
                u32 b0 = Ks[n * 132 + k];
                u32 b1 = Ks[n * 132 + k + 4];
                mma8(S[t], a0, a1, a2, a3, b0, b1);
            }
        }
        __syncthreads();          // all warps done reading Ks

        // ---- prefetch K(mb+64) into Ks (overlaps softmax + PV) ----
        if (more) {
            const float* Kg = Kg0 + (size_t)(mb + 64) * DI;
#pragma unroll
            for (int it = 0; it < 8; ++it) {
                int r = rK + 8 * it;
                cp16(smaddr(&Ks[r * 132 + cK]), Kg + (size_t)r * DI + cK);
            }
            CP_COMMIT();
        }

        // ---- row max ----
        float mx0 = fmaxf(fmaxf(S[0].x, S[0].y), fmaxf(S[1].x, S[1].y));
        mx0 = fmaxf(mx0, fmaxf(fmaxf(S[2].x, S[2].y), fmaxf(S[3].x, S[3].y)));
        float mx1 = fmaxf(fmaxf(S[0].z, S[0].w), fmaxf(S[1].z, S[1].w));
        mx1 = fmaxf(mx1, fmaxf(fmaxf(S[2].z, S[2].w), fmaxf(S[3].z, S[3].w)));
        mx0 = fmaxf(mx0, __shfl_xor_sync(0xffffffffu, mx0, 1));
        mx0 = fmaxf(mx0, __shfl_xor_sync(0xffffffffu, mx0, 2));
        mx1 = fmaxf(mx1, __shfl_xor_sync(0xffffffffu, mx1, 1));
        mx1 = fmaxf(mx1, __shfl_xor_sync(0xffffffffu, mx1, 2));
        if (qd == 0) {
            red[wc * 64 + row0] = mx0;
            red[wc * 64 + row0 + 8] = mx1;
        }
        __syncthreads();
        float newM0 = fmaxf(M0, fmaxf(red[row0], red[64 + row0]));
        float newM1 = fmaxf(M1, fmaxf(red[row0 + 8], red[64 + row0 + 8]));

        // ---- exp + partial sums + store P (raw fp32 bits) ----
        float s0 = 0.0f, s1 = 0.0f;
#pragma unroll
        for (int t = 0; t < 4; ++t) {
            S[t].x = __expf(S[t].x - newM0);
            S[t].y = __expf(S[t].y - newM0);
            S[t].z = __expf(S[t].z - newM1);
            S[t].w = __expf(S[t].w - newM1);
            s0 += S[t].x + S[t].y;
            s1 += S[t].z + S[t].w;
            int col = 32 * wc + 8 * t + 2 * qd;
            *(uint2*)&Ps[row0 * 68 + col] =
                make_uint2(__float_as_uint(S[t].x), __float_as_uint(S[t].y));
            *(uint2*)&Ps[(row0 + 8) * 68 + col] =
                make_uint2(__float_as_uint(S[t].z), __float_as_uint(S[t].w));
        }
        s0 += __shfl_xor_sync(0xffffffffu, s0, 1);
        s0 += __shfl_xor_sync(0xffffffffu, s0, 2);
        s1 += __shfl_xor_sync(0xffffffffu, s1, 1);
        s1 += __shfl_xor_sync(0xffffffffu, s1, 2);
        if (qd == 0) {
            red[128 + wc * 64 + row0] = s0;
            red[128 + wc * 64 + row0 + 8] = s1;
        }
        // V(mb) must be resident for PV; K(mb+64) group may stay in flight
        if (more) CP_WAIT1(); else CP_WAIT0();
        __syncthreads();   // orders P stores + red sums + V arrival for all threads

        float corr0 = __expf(M0 - newM0);
        float corr1 = __expf(M1 - newM1);
        L0 = L0 * corr0 + red[128 + row0] + red[192 + row0];
        L1 = L1 * corr1 + red[128 + row0 + 8] + red[192 + row0 + 8];
        M0 = newM0; M1 = newM1;
#pragma unroll
        for (int t = 0; t < 16; ++t) {
            acc[t].x *= corr0; acc[t].y *= corr0;
            acc[t].z *= corr1; acc[t].w *= corr1;
        }

        // ---- O += P V (warp computes 16x128 at vc base 128*wc) ----
#pragma unroll
        for (int kk = 0; kk < 8; ++kk) {
            int k = kk * 8 + qd;
            u32 a0 = Ps[row0 * 68 + k];
            u32 a1 = Ps[(row0 + 8) * 68 + k];
            u32 a2 = Ps[row0 * 68 + k + 4];
            u32 a3 = Ps[(row0 + 8) * 68 + k + 4];
            int m0 = kk * 8 + qd;
#pragma unroll
            for (int t = 0; t < 16; ++t) {
                int vc = 128 * wc + 8 * t + gq;
                u32 b0 = Vs[m0 * 260 + vc];
                u32 b1 = Vs[(m0 + 4) * 260 + vc];
                mma8(acc[t], a0, a1, a2, a3, b0, b1);
            }
        }
        __syncthreads();          // all warps done reading Vs (and Ps)

        // ---- prefetch V(mb+64) into Vs (overlaps next S) ----
        if (more) {
            const float* Vg = Vg0 + (size_t)(mb + 64) * DV;
#pragma unroll
            for (int it = 0; it < 16; ++it) {
                int r = rV + 4 * it;
                cp16(smaddr(&Vs[r * 260 + cV]), Vg + (size_t)r * DV + cV);
            }
            CP_COMMIT();
        }
    }

    // ---- epilogue: att = csum - acc / L ----
    const float* cs = csum + b * DV;
    float* og = att + ((size_t)b * NTOK + nbase) * DV;
    float inv0 = 1.0f / L0, inv1 = 1.0f / L1;
#pragma unroll
    for (int t = 0; t < 16; ++t) {
        int col = 128 * wc + 8 * t + 2 * qd;
        float2 c0 = *(const float2*)&cs[col];
        float2 r0, r1;
        r0.x = c0.x - acc[t].x * inv0;
        r0.y = c0.y - acc[t].y * inv0;
        r1.x = c0.x - acc[t].z * inv1;
        r1.y = c0.y - acc[t].w * inv1;
        *(float2*)&og[(size_t)row0 * DV + col] = r0;
        *(float2*)&og[(size_t)(row0 + 8) * DV + col] = r1;
    }
}

// out[b][o][n] = relu((sum_c Wp[o][c]*att[b][n][c] + bias[o])*sc[o] + tr[o])
__global__ __launch_bounds__(256)
void projf_kernel(const float* __restrict__ A, const float* __restrict__ W,
                  const float* __restrict__ bias, const float* __restrict__ sc,
                  const float* __restrict__ tr, float* __restrict__ out) {
    __shared__ float As[32 * 68];
    __shared__ float Ws[64 * 33];
    const int b = blockIdx.z;
    const int obase = blockIdx.y * 64;
    const int nbase = blockIdx.x * 64;
    const int tid = threadIdx.x;
    const int tx = tid & 15, ty = tid >> 4;
    const float* Ag = A + (size_t)b * NTOK * DV;

    u64 accp[4][2];
#pragma unroll
    for (int i = 0; i < 4; ++i) { accp[i][0] = 0ull; accp[i][1] = 0ull; }

    for (int c0 = 0; c0 < DV; c0 += 32) {
        __syncthreads();
#pragma unroll
        for (int it = 0; it < 2; ++it) {
            int idx = tid + it * 256;
            int n = idx >> 3, c4 = idx & 7;
            float4 v = *(const float4*)&Ag[(size_t)(nbase + n) * DV + c0 + c4 * 4];
            As[(c4 * 4 + 0) * 68 + n] = v.x;
            As[(c4 * 4 + 1) * 68 + n] = v.y;
            As[(c4 * 4 + 2) * 68 + n] = v.z;
            As[(c4 * 4 + 3) * 68 + n] = v.w;
        }
#pragma unroll
        for (int it = 0; it < 8; ++it) {
            int idx = tid + it * 256;
            int r = idx >> 5, c = idx & 31;
            Ws[r * 33 + c] = W[(size_t)(obase + r) * DV + c0 + c];
        }
        __syncthreads();
#pragma unroll 4
        for (int c = 0; c < 32; ++c) {
            ulonglong2 ap = *(const ulonglong2*)&As[c * 68 + 4 * tx];
#pragma unroll
            for (int i = 0; i < 4; ++i) {
                float w = Ws[(4 * ty + i) * 33 + c];
                u64 w2 = pack2(w, w);
                ffma2(accp[i][0], w2, ap.x);
                ffma2(accp[i][1], w2, ap.y);
            }
        }
    }
#pragma unroll
    for (int i = 0; i < 4; ++i) {
        int o = obase + 4 * ty + i;
        float bb = bias[o], ss = sc[o], tt = tr[o];
        float2 a0 = unpack2(accp[i][0]);
        float2 a1 = unpack2(accp[i][1]);
        float4 r;
        r.x = (a0.x + bb) * ss + tt; r.x = r.x > 0.f ? r.x : 0.f;
        r.y = (a0.y + bb) * ss + tt; r.y = r.y > 0.f ? r.y : 0.f;
        r.z = (a1.x + bb) * ss + tt; r.z = r.z > 0.f ? r.z : 0.f;
        r.w = (a1.y + bb) * ss + tt; r.w = r.w > 0.f ? r.w : 0.f;
        *(float4*)&out[((size_t)b * OUTC + o) * NTOK + nbase + 4 * tx] = r;
    }
}

extern "C" void kernel_launch(void* const* d_in, const int* in_sizes, int n_in,
                              void* d_out, int out_size) {
    const float* x1 = (const float*)d_in[0];
    const float* x2 = (const float*)d_in[1];
    const float* Wq = (const float*)d_in[2];
    const float* bq = (const float*)d_in[3];
    const float* sq = (const float*)d_in[4];
    const float* tq = (const float*)d_in[5];
    const float* Wk = (const float*)d_in[6];
    const float* bk = (const float*)d_in[7];
    const float* sk = (const float*)d_in[8];
    const float* tk = (const float*)d_in[9];
    const float* Wv = (const float*)d_in[10];
    const float* bv = (const float*)d_in[11];
    const float* sv = (const float*)d_in[12];
    const float* tv = (const float*)d_in[13];
    const float* Wp = (const float*)d_in[14];
    const float* bp = (const float*)d_in[15];
    const float* sp = (const float*)d_in[16];
    const float* tp = (const float*)d_in[17];
    float* out = (float*)d_out;

    float *pQ, *pK, *pV, *pAtt, *pCs;
    cudaGetSymbolAddress((void**)&pQ, g_Q);
    cudaGetSymbolAddress((void**)&pK, g_K);
    cudaGetSymbolAddress((void**)&pV, g_V);
    cudaGetSymbolAddress((void**)&pAtt, g_att);
    cudaGetSymbolAddress((void**)&pCs, g_csum);

    const int SMEM_ATTN = (64 * 132 * 2 + 64 * 260 + 64 * 68 + 256) * 4;  // 152576 B
    cudaFuncSetAttribute(attn_kernel, cudaFuncAttributeMaxDynamicSharedMemorySize, SMEM_ATTN);

    qkv_proj_kernel<<<dim3(NTOK / 64, BATCH, 4), 256>>>(
        x1, x2, Wq, bq, sq, tq, Wk, bk, sk, tk, Wv, bv, sv, tv, pQ, pK, pV);
    zero_csum_kernel<<<1, BATCH * DV>>>();
    colsum_kernel<<<dim3(NTOK / 64, BATCH), 256>>>();
    attn_kernel<<<dim3(NTOK / 64, BATCH), 256, SMEM_ATTN>>>(pQ, pK, pV, pCs, pAtt);
    projf_kernel<<<dim3(NTOK / 64, OUTC / 64, BATCH), 256>>>(pAtt, Wp, bp, sp, tp, out);
}